// round 1
// baseline (speedup 1.0000x reference)
#include <cuda_runtime.h>
#include <cuda_bf16.h>

#define G_COUNT 2048
#define NPTS 65536
#define TILE 128
#define BLOCK 64

// Packed per-gaussian params: 7 float4 each
//  [0] = (px, py, cos(th), sin(th))
//  [1] = (sx, sy, colR, colG)
//  [2] = (colB, 0, 0, 0)
//  [3..6] = (w_{2j}, coef_{2j}, w_{2j+1}, coef_{2j+1}), w = fl32(2*pi) * float(idx)
__device__ float4 g_packed[G_COUNT * 7];

__global__ void prep_kernel(const float* __restrict__ col,
                            const float* __restrict__ pos,
                            const float* __restrict__ scl,
                            const float* __restrict__ rot,
                            const float* __restrict__ coef,
                            const int*   __restrict__ idx) {
    int g = blockIdx.x * blockDim.x + threadIdx.x;
    if (g >= G_COUNT) return;
    float th = rot[g];
    float c = cosf(th);
    float s = sinf(th);
    g_packed[g * 7 + 0] = make_float4(pos[2 * g], pos[2 * g + 1], c, s);
    g_packed[g * 7 + 1] = make_float4(scl[2 * g], scl[2 * g + 1], col[3 * g], col[3 * g + 1]);
    g_packed[g * 7 + 2] = make_float4(col[3 * g + 2], 0.f, 0.f, 0.f);
    const float TWO_PI = 6.283185307179586f;  // rounds to fl32(2*pi), matching jax weak-type cast
#pragma unroll
    for (int k = 0; k < 4; k++) {
        float w0 = TWO_PI * (float)idx[8 * g + 2 * k];
        float w1 = TWO_PI * (float)idx[8 * g + 2 * k + 1];
        g_packed[g * 7 + 3 + k] =
            make_float4(w0, coef[8 * g + 2 * k], w1, coef[8 * g + 2 * k + 1]);
    }
}

// cos of arg where arg may reach ~1600 rad: reduce mod 2*pi with 2-word pi so
// MUFU.COS operates in its accurate range. Total error vs precise cos ~4e-7.
__device__ __forceinline__ float fast_cos_reduced(float arg) {
    const float INV_2PI = 0.15915494309189535f;
    const float PI2_HI  = 6.2831855f;        // fl32(2*pi)
    const float PI2_LO  = 1.7484556e-7f;     // fl32(2*pi) - 2*pi (negated)
    float fn = rintf(arg * INV_2PI);
    float r  = fmaf(fn, -PI2_HI, arg);
    r        = fmaf(fn,  PI2_LO, r);
    float co;
    asm("cos.approx.f32 %0, %1;" : "=f"(co) : "f"(r));
    return co;
}

__global__ void __launch_bounds__(BLOCK)
main_kernel(const float2* __restrict__ x, float* __restrict__ out) {
    __shared__ float4 sm[TILE * 7];
    int n = blockIdx.x * BLOCK + threadIdx.x;
    float2 pt = x[n];
    float aR = 0.f, aG = 0.f, aB = 0.f;

    for (int t = 0; t < G_COUNT; t += TILE) {
        __syncthreads();
        // cooperative tile load: 128 gaussians * 7 float4 = 896 float4
#pragma unroll
        for (int i = threadIdx.x; i < TILE * 7; i += BLOCK)
            sm[i] = g_packed[t * 7 + i];
        __syncthreads();

#pragma unroll 2
        for (int gi = 0; gi < TILE; gi++) {
            float4 v0 = sm[gi * 7 + 0];
            float4 v1 = sm[gi * 7 + 1];
            float  cb = sm[gi * 7 + 2].x;

            float dx = pt.x - v0.x;
            float dy = pt.y - v0.y;
            float rx = v0.z * dx + v0.w * dy;
            float ry = v0.z * dy - v0.w * dx;
            float tx = rx * v1.x;
            float ty = ry * v1.y;
            float t2 = fmaf(ty, ty, tx * tx);
            float m  = -0.72134752f * t2;  // -0.5 * log2(e) folded
            float env;
            asm("ex2.approx.f32 %0, %1;" : "=f"(env) : "f"(m));

            float wave = 0.f;
#pragma unroll
            for (int j = 0; j < 4; j++) {
                float4 p = sm[gi * 7 + 3 + j];
                wave = fmaf(p.y, fast_cos_reduced(p.x * rx), wave);
                wave = fmaf(p.w, fast_cos_reduced(p.z * rx), wave);
            }

            float ew = env * wave;
            aR = fmaf(ew, v1.z, aR);
            aG = fmaf(ew, v1.w, aG);
            aB = fmaf(ew, cb, aB);
        }
    }

    out[3 * n + 0] = aR;
    out[3 * n + 1] = aG;
    out[3 * n + 2] = aB;
}

extern "C" void kernel_launch(void* const* d_in, const int* in_sizes, int n_in,
                              void* d_out, int out_size) {
    const float* x    = (const float*)d_in[0];
    const float* col  = (const float*)d_in[1];
    const float* pos  = (const float*)d_in[2];
    const float* scl  = (const float*)d_in[3];
    const float* rot  = (const float*)d_in[4];
    const float* coef = (const float*)d_in[5];
    const int*   idx  = (const int*)d_in[6];

    prep_kernel<<<(G_COUNT + 255) / 256, 256>>>(col, pos, scl, rot, coef, idx);
    main_kernel<<<NPTS / BLOCK, BLOCK>>>((const float2*)x, (float*)d_out);
}

// round 2
// speedup vs baseline: 1.3852x; 1.3852x over previous
#include <cuda_runtime.h>
#include <cuda_bf16.h>

#define G_COUNT 2048
#define NPTS 65536
#define TILE 64
#define BLOCK 32

typedef unsigned long long u64;

// Per-gaussian packed params: 13 ulonglong2, each .x/.y is an f32x2 with the
// SAME scalar duplicated in both halves (so packed math needs no broadcast MOVs).
//  [0] = (-px, -py)   [1] = (cos, sin)   [2] = (-sin, sx)
//  [3] = (sy, colR)   [4] = (colG, colB)
//  [5+k] = (w_k, coef_k), k=0..7, w = fl32(2*pi) * float(idx)
__device__ ulonglong2 g_packed2[G_COUNT * 13];

__device__ __forceinline__ u64 pk(float a, float b) {
    u64 r; asm("mov.b64 %0,{%1,%2};" : "=l"(r) : "f"(a), "f"(b)); return r;
}
__device__ __forceinline__ void upk(u64 v, float& a, float& b) {
    asm("mov.b64 {%0,%1},%2;" : "=f"(a), "=f"(b) : "l"(v));
}
__device__ __forceinline__ u64 add2(u64 a, u64 b) {
    u64 r; asm("add.rn.f32x2 %0,%1,%2;" : "=l"(r) : "l"(a), "l"(b)); return r;
}
__device__ __forceinline__ u64 mul2(u64 a, u64 b) {
    u64 r; asm("mul.rn.f32x2 %0,%1,%2;" : "=l"(r) : "l"(a), "l"(b)); return r;
}
__device__ __forceinline__ u64 fma2(u64 a, u64 b, u64 c) {
    u64 r; asm("fma.rn.f32x2 %0,%1,%2,%3;" : "=l"(r) : "l"(a), "l"(b), "l"(c)); return r;
}
__device__ __forceinline__ float cosap(float x) {
    float c; asm("cos.approx.f32 %0,%1;" : "=f"(c) : "f"(x)); return c;
}
__device__ __forceinline__ float ex2ap(float x) {
    float c; asm("ex2.approx.f32 %0,%1;" : "=f"(c) : "f"(x)); return c;
}
__device__ __forceinline__ u64 dup(float a) { return pk(a, a); }

__global__ void prep_kernel(const float* __restrict__ col,
                            const float* __restrict__ pos,
                            const float* __restrict__ scl,
                            const float* __restrict__ rot,
                            const float* __restrict__ coef,
                            const int*   __restrict__ idx) {
    int g = blockIdx.x * blockDim.x + threadIdx.x;
    if (g >= G_COUNT) return;
    float th = rot[g];
    float c = cosf(th);
    float s = sinf(th);
    ulonglong2* gp = &g_packed2[g * 13];
    gp[0] = make_ulonglong2(dup(-pos[2 * g]), dup(-pos[2 * g + 1]));
    gp[1] = make_ulonglong2(dup(c), dup(s));
    gp[2] = make_ulonglong2(dup(-s), dup(scl[2 * g]));
    gp[3] = make_ulonglong2(dup(scl[2 * g + 1]), dup(col[3 * g]));
    gp[4] = make_ulonglong2(dup(col[3 * g + 1]), dup(col[3 * g + 2]));
    const float TWO_PI = 6.283185307179586f;  // fl32(2*pi), matches jax fp32 cast
#pragma unroll
    for (int k = 0; k < 8; k++) {
        float w = TWO_PI * (float)idx[8 * g + k];
        gp[5 + k] = make_ulonglong2(dup(w), dup(coef[8 * g + k]));
    }
}

__global__ void __launch_bounds__(BLOCK)
main_kernel(const float* __restrict__ x, float* __restrict__ out) {
    __shared__ ulonglong2 sm[TILE * 13];
    int lane = threadIdx.x;
    int n0 = blockIdx.x * 64 + lane;
    int n1 = n0 + 32;

    u64 ax2 = pk(x[2 * n0],     x[2 * n1]);
    u64 ay2 = pk(x[2 * n0 + 1], x[2 * n1 + 1]);

    const u64 INV2PI2 = dup(0.15915494309189535f);
    const u64 MAGIC2  = dup(12582912.0f);           // 1.5 * 2^23: rint via RN
    const u64 NMAGIC2 = dup(-12582912.0f);
    const u64 NHI2    = dup(-6.2831855f);            // -fl32(2*pi)
    const u64 LO2     = dup(1.7484556e-7f);          // fl32(2*pi) - 2*pi
    const u64 NEGK2   = dup(-0.72134752f);           // -0.5*log2(e)
    const u64 ZERO2   = dup(0.0f);

    u64 aR = ZERO2, aG = ZERO2, aB = ZERO2;

    for (int t = 0; t < G_COUNT; t += TILE) {
        __syncwarp();
        for (int i = lane; i < TILE * 13; i += BLOCK)
            sm[i] = g_packed2[t * 13 + i];
        __syncwarp();

        for (int gi = 0; gi < TILE; gi++) {
            const ulonglong2* gp = &sm[gi * 13];
            ulonglong2 q0 = gp[0], q1 = gp[1], q2 = gp[2], q3 = gp[3], q4 = gp[4];

            u64 dx2 = add2(ax2, q0.x);
            u64 dy2 = add2(ay2, q0.y);
            u64 rx2 = fma2(q1.x, dx2, mul2(q1.y, dy2));   //  c*dx + s*dy
            u64 ry2 = fma2(q1.x, dy2, mul2(q2.x, dx2));   //  c*dy - s*dx
            u64 tx2 = mul2(rx2, q2.y);
            u64 ty2 = mul2(ry2, q3.x);
            u64 m2  = mul2(fma2(ty2, ty2, mul2(tx2, tx2)), NEGK2);
            float m0, m1; upk(m2, m0, m1);
            u64 env2 = pk(ex2ap(m0), ex2ap(m1));

            u64 wave2 = ZERO2;
#pragma unroll
            for (int k = 0; k < 8; k++) {
                ulonglong2 wc = gp[5 + k];
                u64 arg2 = mul2(wc.x, rx2);                 // same rounding as ref phase
                u64 tq2  = fma2(arg2, INV2PI2, MAGIC2);
                u64 n2   = add2(tq2, NMAGIC2);              // n = rint(arg/2pi)
                u64 r2   = fma2(n2, NHI2, arg2);            // 2-word reduction
                r2       = fma2(n2, LO2, r2);
                float ra, rb; upk(r2, ra, rb);
                u64 co2 = pk(cosap(ra), cosap(rb));
                wave2 = fma2(wc.y, co2, wave2);
            }

            u64 ew2 = mul2(env2, wave2);
            aR = fma2(ew2, q3.y, aR);
            aG = fma2(ew2, q4.x, aG);
            aB = fma2(ew2, q4.y, aB);
        }
    }

    float r0, r1, g0, g1, b0, b1;
    upk(aR, r0, r1); upk(aG, g0, g1); upk(aB, b0, b1);
    out[3 * n0 + 0] = r0; out[3 * n0 + 1] = g0; out[3 * n0 + 2] = b0;
    out[3 * n1 + 0] = r1; out[3 * n1 + 1] = g1; out[3 * n1 + 2] = b1;
}

extern "C" void kernel_launch(void* const* d_in, const int* in_sizes, int n_in,
                              void* d_out, int out_size) {
    const float* x    = (const float*)d_in[0];
    const float* col  = (const float*)d_in[1];
    const float* pos  = (const float*)d_in[2];
    const float* scl  = (const float*)d_in[3];
    const float* rot  = (const float*)d_in[4];
    const float* coef = (const float*)d_in[5];
    const int*   idx  = (const int*)d_in[6];

    prep_kernel<<<(G_COUNT + 255) / 256, 256>>>(col, pos, scl, rot, coef, idx);
    main_kernel<<<NPTS / 64, BLOCK>>>(x, (float*)d_out);
}

// round 3
// speedup vs baseline: 1.7009x; 1.2279x over previous
#include <cuda_runtime.h>
#include <cuda_bf16.h>

#define G_COUNT 2048
#define NPTS 65536
#define TILE 64
#define BLOCK 32
#define SPLIT 4
#define GPS (G_COUNT / SPLIT)   // 512 gaussians per split

typedef unsigned long long u64;

// Per-gaussian packed params: 13 ulonglong2, each .x/.y is an f32x2 with the
// SAME scalar duplicated in both halves (so packed math needs no broadcast MOVs).
//  [0] = (-px, -py)   [1] = (cos, sin)   [2] = (-sin, sx)
//  [3] = (sy, colR)   [4] = (colG, colB)
//  [5+k] = (w_k, coef_k), k=0..7, w = fl32(2*pi) * float(idx)
__device__ ulonglong2 g_packed2[G_COUNT * 13];
__device__ float g_part[SPLIT * NPTS * 3];   // per-split partial colors

__device__ __forceinline__ u64 pk(float a, float b) {
    u64 r; asm("mov.b64 %0,{%1,%2};" : "=l"(r) : "f"(a), "f"(b)); return r;
}
__device__ __forceinline__ void upk(u64 v, float& a, float& b) {
    asm("mov.b64 {%0,%1},%2;" : "=f"(a), "=f"(b) : "l"(v));
}
__device__ __forceinline__ u64 add2(u64 a, u64 b) {
    u64 r; asm("add.rn.f32x2 %0,%1,%2;" : "=l"(r) : "l"(a), "l"(b)); return r;
}
__device__ __forceinline__ u64 mul2(u64 a, u64 b) {
    u64 r; asm("mul.rn.f32x2 %0,%1,%2;" : "=l"(r) : "l"(a), "l"(b)); return r;
}
__device__ __forceinline__ u64 fma2(u64 a, u64 b, u64 c) {
    u64 r; asm("fma.rn.f32x2 %0,%1,%2,%3;" : "=l"(r) : "l"(a), "l"(b), "l"(c)); return r;
}
__device__ __forceinline__ float cosap(float x) {
    float c; asm("cos.approx.f32 %0,%1;" : "=f"(c) : "f"(x)); return c;
}
__device__ __forceinline__ float ex2ap(float x) {
    float c; asm("ex2.approx.f32 %0,%1;" : "=f"(c) : "f"(x)); return c;
}
__device__ __forceinline__ u64 dup(float a) { return pk(a, a); }

__global__ void prep_kernel(const float* __restrict__ col,
                            const float* __restrict__ pos,
                            const float* __restrict__ scl,
                            const float* __restrict__ rot,
                            const float* __restrict__ coef,
                            const int*   __restrict__ idx) {
    int g = blockIdx.x * blockDim.x + threadIdx.x;
    if (g >= G_COUNT) return;
    float th = rot[g];
    float c = cosf(th);
    float s = sinf(th);
    ulonglong2* gp = &g_packed2[g * 13];
    gp[0] = make_ulonglong2(dup(-pos[2 * g]), dup(-pos[2 * g + 1]));
    gp[1] = make_ulonglong2(dup(c), dup(s));
    gp[2] = make_ulonglong2(dup(-s), dup(scl[2 * g]));
    gp[3] = make_ulonglong2(dup(scl[2 * g + 1]), dup(col[3 * g]));
    gp[4] = make_ulonglong2(dup(col[3 * g + 1]), dup(col[3 * g + 2]));
    const float TWO_PI = 6.283185307179586f;  // fl32(2*pi), matches jax fp32 cast
#pragma unroll
    for (int k = 0; k < 8; k++) {
        float w = TWO_PI * (float)idx[8 * g + k];
        gp[5 + k] = make_ulonglong2(dup(w), dup(coef[8 * g + k]));
    }
}

__global__ void __launch_bounds__(BLOCK)
main_kernel(const float* __restrict__ x) {
    __shared__ ulonglong2 sm[TILE * 13];
    int lane = threadIdx.x;
    int bid  = blockIdx.x;
    int s    = bid & (SPLIT - 1);          // gaussian split
    int chunk = bid >> 2;                  // point chunk
    int n0 = chunk * 64 + lane;
    int n1 = n0 + 32;

    u64 ax2 = pk(x[2 * n0],     x[2 * n1]);
    u64 ay2 = pk(x[2 * n0 + 1], x[2 * n1 + 1]);

    const u64 INV2PI2 = dup(0.15915494309189535f);
    const u64 MAGIC2  = dup(12582912.0f);            // 1.5 * 2^23: rint via RN
    const u64 NMAGIC2 = dup(-12582912.0f);
    const u64 NHI2    = dup(-6.2831855f);            // -fl32(2*pi)
    const u64 LO2     = dup(1.7484556e-7f);          // fl32(2*pi) - 2*pi
    const u64 NEGK2   = dup(-0.72134752f);           // -0.5*log2(e)
    const u64 ZERO2   = dup(0.0f);

    u64 aR = ZERO2, aG = ZERO2, aB = ZERO2;

    int gbeg = s * GPS;
    for (int t = gbeg; t < gbeg + GPS; t += TILE) {
        __syncwarp();
        for (int i = lane; i < TILE * 13; i += BLOCK)
            sm[i] = g_packed2[t * 13 + i];
        __syncwarp();

        for (int gi = 0; gi < TILE; gi++) {
            const ulonglong2* gp = &sm[gi * 13];
            ulonglong2 q0 = gp[0], q1 = gp[1], q2 = gp[2], q3 = gp[3], q4 = gp[4];

            u64 dx2 = add2(ax2, q0.x);
            u64 dy2 = add2(ay2, q0.y);
            u64 rx2 = fma2(q1.x, dx2, mul2(q1.y, dy2));   //  c*dx + s*dy
            u64 ry2 = fma2(q1.x, dy2, mul2(q2.x, dx2));   //  c*dy - s*dx
            u64 tx2 = mul2(rx2, q2.y);
            u64 ty2 = mul2(ry2, q3.x);
            u64 m2  = mul2(fma2(ty2, ty2, mul2(tx2, tx2)), NEGK2);
            float m0, m1; upk(m2, m0, m1);
            u64 env2 = pk(ex2ap(m0), ex2ap(m1));

            u64 wave2 = ZERO2;
#pragma unroll
            for (int k = 0; k < 8; k++) {
                ulonglong2 wc = gp[5 + k];
                u64 arg2 = mul2(wc.x, rx2);                 // same rounding as ref phase
                u64 tq2  = fma2(arg2, INV2PI2, MAGIC2);
                u64 n2   = add2(tq2, NMAGIC2);              // n = rint(arg/2pi)
                u64 r2   = fma2(n2, NHI2, arg2);            // 2-word reduction
                r2       = fma2(n2, LO2, r2);
                float ra, rb; upk(r2, ra, rb);
                u64 co2 = pk(cosap(ra), cosap(rb));
                wave2 = fma2(wc.y, co2, wave2);
            }

            u64 ew2 = mul2(env2, wave2);
            aR = fma2(ew2, q3.y, aR);
            aG = fma2(ew2, q4.x, aG);
            aB = fma2(ew2, q4.y, aB);
        }
    }

    float r0, r1, g0, g1, b0, b1;
    upk(aR, r0, r1); upk(aG, g0, g1); upk(aB, b0, b1);
    float* p = &g_part[s * NPTS * 3];
    p[3 * n0 + 0] = r0; p[3 * n0 + 1] = g0; p[3 * n0 + 2] = b0;
    p[3 * n1 + 0] = r1; p[3 * n1 + 1] = g1; p[3 * n1 + 2] = b1;
}

__global__ void reduce_kernel(float* __restrict__ out) {
    int i = blockIdx.x * blockDim.x + threadIdx.x;
    if (i >= NPTS * 3) return;
    float acc = g_part[i];
    acc += g_part[NPTS * 3 + i];
    acc += g_part[2 * NPTS * 3 + i];
    acc += g_part[3 * NPTS * 3 + i];
    out[i] = acc;
}

extern "C" void kernel_launch(void* const* d_in, const int* in_sizes, int n_in,
                              void* d_out, int out_size) {
    const float* x    = (const float*)d_in[0];
    const float* col  = (const float*)d_in[1];
    const float* pos  = (const float*)d_in[2];
    const float* scl  = (const float*)d_in[3];
    const float* rot  = (const float*)d_in[4];
    const float* coef = (const float*)d_in[5];
    const int*   idx  = (const int*)d_in[6];

    prep_kernel<<<(G_COUNT + 255) / 256, 256>>>(col, pos, scl, rot, coef, idx);
    main_kernel<<<(NPTS / 64) * SPLIT, BLOCK>>>(x);
    reduce_kernel<<<(NPTS * 3 + 255) / 256, 256>>>((float*)d_out);
}

// round 4
// speedup vs baseline: 1.8144x; 1.0667x over previous
#include <cuda_runtime.h>
#include <cuda_bf16.h>

#define G_COUNT 2048
#define NPTS 65536
#define TILE 32
#define BLOCK 32
#define SPLIT 8
#define GPS (G_COUNT / SPLIT)   // 256 gaussians per split

typedef unsigned long long u64;

// Per-gaussian packed params: 14 ulonglong2; every u64 is f32x2 with the SAME
// scalar in both halves. K = sqrt(0.5*log2(e)) folded into scales.
//  [0] (-px,-py) [1] (c,s) [2] (K*c*sx, K*s*sx) [3] (K*c*sy, -K*s*sy)
//  [4] (colR,colG) [5] (colB, 0) [6+k] (float(m_k), coef_k)
__device__ ulonglong2 g_packed2[G_COUNT * 14];
__device__ float g_part[SPLIT * NPTS * 3];

__device__ __forceinline__ u64 pk(float a, float b) {
    u64 r; asm("mov.b64 %0,{%1,%2};" : "=l"(r) : "f"(a), "f"(b)); return r;
}
__device__ __forceinline__ void upk(u64 v, float& a, float& b) {
    asm("mov.b64 {%0,%1},%2;" : "=f"(a), "=f"(b) : "l"(v));
}
__device__ __forceinline__ u64 add2(u64 a, u64 b) {
    u64 r; asm("add.rn.f32x2 %0,%1,%2;" : "=l"(r) : "l"(a), "l"(b)); return r;
}
__device__ __forceinline__ u64 mul2(u64 a, u64 b) {
    u64 r; asm("mul.rn.f32x2 %0,%1,%2;" : "=l"(r) : "l"(a), "l"(b)); return r;
}
__device__ __forceinline__ u64 fma2(u64 a, u64 b, u64 c) {
    u64 r; asm("fma.rn.f32x2 %0,%1,%2,%3;" : "=l"(r) : "l"(a), "l"(b), "l"(c)); return r;
}
__device__ __forceinline__ float cosap(float x) {
    float c; asm("cos.approx.f32 %0,%1;" : "=f"(c) : "f"(x)); return c;
}
__device__ __forceinline__ float ex2ap(float x) {
    float c; asm("ex2.approx.f32 %0,%1;" : "=f"(c) : "f"(x)); return c;
}
__device__ __forceinline__ u64 dup(float a) { return pk(a, a); }

__global__ void prep_kernel(const float* __restrict__ col,
                            const float* __restrict__ pos,
                            const float* __restrict__ scl,
                            const float* __restrict__ rot,
                            const float* __restrict__ coef,
                            const int*   __restrict__ idx) {
    int g = blockIdx.x * blockDim.x + threadIdx.x;
    if (g >= G_COUNT) return;
    float th = rot[g];
    float c = cosf(th);
    float s = sinf(th);
    const float K = 0.8493218f;   // sqrt(0.5 * log2(e))
    float sx = scl[2 * g] * K;
    float sy = scl[2 * g + 1] * K;
    ulonglong2* gp = &g_packed2[g * 14];
    gp[0] = make_ulonglong2(dup(-pos[2 * g]), dup(-pos[2 * g + 1]));
    gp[1] = make_ulonglong2(dup(c), dup(s));
    gp[2] = make_ulonglong2(dup(c * sx), dup(s * sx));
    gp[3] = make_ulonglong2(dup(c * sy), dup(-s * sy));
    gp[4] = make_ulonglong2(dup(col[3 * g]), dup(col[3 * g + 1]));
    gp[5] = make_ulonglong2(dup(col[3 * g + 2]), dup(0.f));
#pragma unroll
    for (int k = 0; k < 8; k++)
        gp[6 + k] = make_ulonglong2(dup((float)idx[8 * g + k]), dup(coef[8 * g + k]));
}

__global__ void __launch_bounds__(BLOCK, 20)
main_kernel(const float* __restrict__ x) {
    __shared__ ulonglong2 sm[TILE * 14];
    int lane = threadIdx.x;
    int bid  = blockIdx.x;
    int s    = bid & (SPLIT - 1);
    int chunk = bid >> 3;
    int n0 = chunk * 64 + lane;
    int n1 = n0 + 32;

    u64 ax2 = pk(x[2 * n0],     x[2 * n1]);
    u64 ay2 = pk(x[2 * n0 + 1], x[2 * n1 + 1]);

    const u64 MAGIC2 = dup(12582912.0f);     // 1.5 * 2^23
    const u64 NEG1_2 = dup(-1.0f);
    const u64 PI2T   = dup(6.2831853f);      // 2*pi (phase |p|<=0.5 -> exact-range)
    const u64 ZERO2  = dup(0.0f);

    u64 aR = ZERO2, aG = ZERO2, aB = ZERO2;

    int gbeg = s * GPS;
    for (int t = gbeg; t < gbeg + GPS; t += TILE) {
        __syncwarp();
        for (int i = lane; i < TILE * 14; i += BLOCK)
            sm[i] = g_packed2[t * 14 + i];
        __syncwarp();

#pragma unroll 2
        for (int gi = 0; gi < TILE; gi++) {
            const ulonglong2* gp = &sm[gi * 14];
            ulonglong2 q0 = gp[0], q1 = gp[1], q2 = gp[2], q3 = gp[3];
            ulonglong2 q4 = gp[4], q5 = gp[5];

            u64 dx2 = add2(ax2, q0.x);
            u64 dy2 = add2(ay2, q0.y);
            u64 rx2 = fma2(q1.x, dx2, mul2(q1.y, dy2));   // c*dx + s*dy (phase coord)
            u64 tx2 = fma2(q2.x, dx2, mul2(q2.y, dy2));   // K*sx*rx
            u64 ty2 = fma2(q3.x, dy2, mul2(q3.y, dx2));   // K*sy*ry
            u64 m2  = fma2(ty2, ty2, mul2(tx2, tx2));     // K^2*(...)  (>=0)
            float m0, m1; upk(m2, m0, m1);
            u64 env2 = pk(ex2ap(-m0), ex2ap(-m1));        // exp(-0.5*(...))

            u64 wave2 = ZERO2;
#pragma unroll
            for (int k = 0; k < 8; k++) {
                ulonglong2 wc = gp[6 + k];
                u64 tq2 = fma2(wc.x, rx2, MAGIC2);        // round(m*rx) + magic
                u64 nn2 = fma2(tq2, NEG1_2, MAGIC2);      // = -round(m*rx), exact
                u64 p2  = fma2(wc.x, rx2, nn2);           // frac in [-0.5,0.5], 1 rounding
                u64 r2  = mul2(p2, PI2T);
                float ra, rb; upk(r2, ra, rb);
                u64 co2 = pk(cosap(ra), cosap(rb));
                wave2 = fma2(wc.y, co2, wave2);
            }

            u64 ew2 = mul2(env2, wave2);
            aR = fma2(ew2, q4.x, aR);
            aG = fma2(ew2, q4.y, aG);
            aB = fma2(ew2, q5.x, aB);
        }
    }

    float r0, r1, g0, g1, b0, b1;
    upk(aR, r0, r1); upk(aG, g0, g1); upk(aB, b0, b1);
    float* p = &g_part[s * NPTS * 3];
    p[3 * n0 + 0] = r0; p[3 * n0 + 1] = g0; p[3 * n0 + 2] = b0;
    p[3 * n1 + 0] = r1; p[3 * n1 + 1] = g1; p[3 * n1 + 2] = b1;
}

__global__ void reduce_kernel(float* __restrict__ out) {
    int i = blockIdx.x * blockDim.x + threadIdx.x;   // float4 index
    if (i >= NPTS * 3 / 4) return;
    const float4* gp = (const float4*)g_part;
    float4 a = gp[i];
#pragma unroll
    for (int sIdx = 1; sIdx < SPLIT; sIdx++) {
        float4 b = gp[sIdx * (NPTS * 3 / 4) + i];
        a.x += b.x; a.y += b.y; a.z += b.z; a.w += b.w;
    }
    ((float4*)out)[i] = a;
}

extern "C" void kernel_launch(void* const* d_in, const int* in_sizes, int n_in,
                              void* d_out, int out_size) {
    const float* x    = (const float*)d_in[0];
    const float* col  = (const float*)d_in[1];
    const float* pos  = (const float*)d_in[2];
    const float* scl  = (const float*)d_in[3];
    const float* rot  = (const float*)d_in[4];
    const float* coef = (const float*)d_in[5];
    const int*   idx  = (const int*)d_in[6];

    prep_kernel<<<(G_COUNT + 255) / 256, 256>>>(col, pos, scl, rot, coef, idx);
    main_kernel<<<(NPTS / 64) * SPLIT, BLOCK>>>(x);
    reduce_kernel<<<(NPTS * 3 / 4 + 255) / 256, 256>>>((float*)d_out);
}